// round 15
// baseline (speedup 1.0000x reference)
#include <cuda_runtime.h>
#include <math.h>

// ---------------- problem constants ----------------
#define BB 4
#define HH 256
#define WW 256
#define HWSZ (HH*WW)

typedef unsigned long long ull;

// ---------------- scratch buffers ----------------
__device__ float g_cat   [(size_t)BB*128*HWSZ]; // raw f1|f2 (for blur/corr)
__device__ float g_cattf [(size_t)BB*128*HWSZ]; // tf32-rounded f1|f2 (for fc1)
__device__ float g_x128  [(size_t)BB*128*HWSZ];
__device__ float g_corr  [(size_t)BB*128*HWSZ]; // feat(rounded) | lc(raw) | zero
__device__ float g_f1s   [(size_t)BB*64*HWSZ];
__device__ float g_x64   [(size_t)BB*64*HWSZ];
__device__ float g_x32   [(size_t)BB*32*HWSZ];
__device__ float g_x16   [(size_t)BB*16*HWSZ];
__device__ float g_head  [(size_t)BB*2*HWSZ];
__device__ float g_lcsum[BB];
__device__ float g_wp[36864 + 147456 + 73728 + 73728 + 18432 + 4608];

__constant__ float GK[7] = {0.03663285f, 0.11128102f, 0.21674443f, 0.27068263f,
                            0.21674443f, 0.11128102f, 0.03663285f};

// ---------------- helpers ----------------
__device__ __forceinline__ unsigned f2tf(float f) {
    unsigned r; asm("cvt.rna.tf32.f32 %0, %1;" : "=r"(r) : "f"(f)); return r;
}
__device__ __forceinline__ float rndtf(float f) { return __uint_as_float(f2tf(f)); }
__device__ __forceinline__ void mma8(float* d, const unsigned* a, const unsigned* b) {
    asm volatile("mma.sync.aligned.m16n8k8.row.col.f32.tf32.tf32.f32 "
        "{%0,%1,%2,%3}, {%4,%5,%6,%7}, {%8,%9}, {%0,%1,%2,%3};\n"
        : "+f"(d[0]), "+f"(d[1]), "+f"(d[2]), "+f"(d[3])
        : "r"(a[0]), "r"(a[1]), "r"(a[2]), "r"(a[3]), "r"(b[0]), "r"(b[1]));
}
__device__ __forceinline__ ull pk2(float lo, float hi) {
    ull r; asm("mov.b64 %0, {%1, %2};" : "=l"(r) : "f"(lo), "f"(hi)); return r;
}
__device__ __forceinline__ void up2(float& lo, float& hi, ull v) {
    asm("mov.b64 {%0, %1}, %2;" : "=f"(lo), "=f"(hi) : "l"(v));
}
__device__ __forceinline__ void fma2(ull& d, ull a, ull b) {
    asm("fma.rn.f32x2 %0, %1, %2, %0;" : "+l"(d) : "l"(a), "l"(b));
}
__device__ __forceinline__ ull add2(ull a, ull b) {
    ull r; asm("add.rn.f32x2 %0, %1, %2;" : "=l"(r) : "l"(a), "l"(b)); return r;
}
__device__ __forceinline__ unsigned smem_u32(const void* p) {
    return (unsigned)__cvta_generic_to_shared(p);
}
__device__ __forceinline__ void cpasync16(unsigned dst, const void* src) {
    asm volatile("cp.async.cg.shared.global [%0], [%1], 16;" :: "r"(dst), "l"(src));
}
__device__ __forceinline__ void cpasync16_z(unsigned dst, const void* src) {
    asm volatile("cp.async.cg.shared.global [%0], [%1], 16, 0;" :: "r"(dst), "l"(src));
}

// ---------------- merged weight prep, fragment-swizzled layout -------------
__device__ __forceinline__ void prep_one(const float* src, float* dst, int r,
                                         int COUT, int CIN)
{
    int j     = r & 3;
    int lane  = (r >> 2) & 31;
    int t     = r >> 7;
    int nblk  = COUT >> 4;
    int coblk = t % nblk;  t /= nblk;
    int ks    = t & 1;     t >>= 1;
    int k9    = t % 9;
    int chunk = t / 9;
    int ci = chunk*16 + ks*8 + (lane & 3) + ((j >> 1) ? 4 : 0);
    int co = coblk*16 + (lane >> 2) + ((j & 1) ? 8 : 0);
    float v = (ci < CIN) ? src[((size_t)(co*CIN + ci))*9 + k9] : 0.f;
    dst[r] = rndtf(v);
}

__global__ void prep_all_kernel(const float* __restrict__ w_pre,
                                const float* __restrict__ w_fc1,
                                const float* __restrict__ w_fc2,
                                const float* __restrict__ w_e1,
                                const float* __restrict__ w_e2,
                                const float* __restrict__ w_e3,
                                float* __restrict__ wp)
{
    int idx = blockIdx.x*256 + threadIdx.x;
    if      (idx < 36864)  prep_one(w_pre, wp,          idx,          64, 64);
    else if (idx < 184320) prep_one(w_fc1, wp + 36864,  idx - 36864, 128, 128);
    else if (idx < 258048) prep_one(w_fc2, wp + 184320, idx - 184320, 64, 128);
    else if (idx < 331776) prep_one(w_e1,  wp + 258048, idx - 258048, 64, 113);
    else if (idx < 350208) prep_one(w_e2,  wp + 331776, idx - 331776, 32, 64);
    else if (idx < 354816) prep_one(w_e3,  wp + 350208, idx - 350208, 16, 32);
}

// ---------------- tf32 tensor-core 3x3 conv --------------------------------
// RY=1: 256 thr, 1 output row/CTA, single-buffered (best for COUT=128)
// RY=2: 512 thr, 2 output rows/CTA, fully double-buffered pipeline
#define KC 16
#define PWD 136

template<int COUT, int CIN, int DIL, int WMODE, int FCVT, int RY>
__global__ __launch_bounds__(256*RY)
void conv_mma(const float* __restrict__ in, int CinS, int cinOff,
              const float* __restrict__ wp, const float* __restrict__ bias,
              float* __restrict__ out, int CoutS, int coutOff,
              float* __restrict__ out2, const float* __restrict__ lcs)
{
    constexpr int NT  = 256*RY;
    constexpr int WM = (COUT >= 32) ? 32 : COUT;
    constexpr int NMW = COUT / WM;
    constexpr int NNW = 8 / NMW;
    constexpr int WN  = 128 / NNW;
    constexpr int MTILES = WM / 16;
    constexpr int NTILES = WN / 8;
    constexpr int NBLK = COUT / 16;
    constexpr int WCHUNK4 = 9*2*NBLK*32;           // 16B units per weight chunk
    constexpr int WCH = WCHUNK4*4;                 // floats per weight chunk
    constexpr int NROWS = (RY == 1) ? 3*KC : (2 + 2*DIL)*KC;
    constexpr int ITERS = NROWS*32/NT;             // async main-fill iterations
    constexpr int SIT   = NROWS/(NT/128);          // scalar main-fill iterations
    constexpr int HSH = (DIL==1) ? 1 : (DIL==2) ? 2 : 3;
    constexpr int NHALO = NROWS*2*DIL;
    constexpr int MBASE = 4 - DIL;
    constexpr bool PIPE = (RY == 2);
    constexpr int NCH = CIN/KC;

    extern __shared__ __align__(16) unsigned smem_u[];
    unsigned* s_inb[2];
    unsigned* s_wb[2];
    s_inb[0] = smem_u;
    s_inb[1] = PIPE ? smem_u + NROWS*PWD : smem_u;
    unsigned* wbase = smem_u + (PIPE ? 2 : 1)*NROWS*PWD;
    s_wb[0] = wbase;
    s_wb[1] = PIPE ? wbase + WCH : wbase;

    const int tid = threadIdx.x;
    const int x0  = blockIdx.x * 128;
    const int y0  = blockIdx.y * RY;
    const int bz  = blockIdx.z;
    const int wid = tid >> 5, lane = tid & 31;
    const int g = lane >> 2, c = lane & 3;
    const int wy = (RY == 2) ? (wid >> 3) : 0;
    const int w8 = (RY == 2) ? (wid & 7) : wid;
    const int wm = w8 % NMW, wn = w8 / NMW;

    float s_scale = 1.f;
    if (FCVT == 2) {
        float mean = lcs[bz]*(1.f/(49.f*HWSZ));
        s_scale = 1.f/(mean + 1e-6f);
    }

    float acc[MTILES][NTILES][4];
#pragma unroll
    for (int mt=0; mt<MTILES; mt++)
#pragma unroll
        for (int nt=0; nt<NTILES; nt++)
#pragma unroll
            for (int r=0; r<4; r++) acc[mt][nt][r] = 0.f;

    auto gyOf = [&](int row) {
        return (RY == 1) ? (y0 + (row-1)*DIL) : (y0 - DIL + row);
    };
    auto fill_weights = [&](int cidx, unsigned* wbuf) {
        const float4* wsrc = (const float4*)wp + (size_t)cidx*WCHUNK4;
        for (int idx = tid; idx < WCHUNK4; idx += NT)
            cpasync16(smem_u32((float*)wbuf + idx*4), wsrc + idx);
    };
    auto fill_input = [&](int cidx, unsigned* ibuf) {
        const int ci0 = cidx*KC;
        const float* ibase = in + ((size_t)(bz*CinS + cinOff + ci0))*HWSZ;
        const bool async_c = (FCVT == 0) || (FCVT == 2 && ci0 < 64);
        if (async_c) {
#pragma unroll
            for (int it = 0; it < ITERS; it++) {
                const int idx    = tid + it*NT;
                const int chunk  = idx & 31;
                const int rowIdx = idx >> 5;
                const int row = rowIdx >> 4;
                const int ci  = rowIdx & 15;
                const int gy  = gyOf(row);
                unsigned dst = smem_u32((float*)ibuf + rowIdx*PWD + 4 + chunk*4);
                const float* src = ibase + (size_t)ci*HWSZ
                                 + (size_t)min(max(gy,0),HH-1)*WW + x0 + chunk*4;
                if ((unsigned)gy < HH) cpasync16(dst, src);
                else                   cpasync16_z(dst, src);
            }
        } else {
            const int pxm = tid & 127;
            const int r0  = tid >> 7;
#pragma unroll
            for (int it = 0; it < SIT; it++) {
                const int rowIdx = it*(NT/128) + r0;
                const int row = rowIdx >> 4;
                const int ci  = rowIdx & 15;
                const int gy  = gyOf(row);
                const int gci = ci0 + ci;
                float v = 0.f;
                bool ok = ((unsigned)gy < HH);
                if (FCVT == 2) ok = ok && (gci < 113);
                if (ok) {
                    float raw = ibase[(size_t)ci*HWSZ + (size_t)gy*WW + x0 + pxm];
                    v = rndtf((FCVT == 2) ? raw*s_scale : raw);
                }
                ibuf[rowIdx*PWD + 4 + pxm] = __float_as_uint(v);
            }
        }
    };
    auto fill_halo = [&](int cidx, unsigned* ibuf) {
        const int ci0 = cidx*KC;
        const float* ibase = in + ((size_t)(bz*CinS + cinOff + ci0))*HWSZ;
        const bool xf = (FCVT == 1) || (FCVT == 2 && ci0 >= 64);
        for (int idx = tid; idx < NHALO; idx += NT) {
            const int off    = idx & (2*DIL - 1);
            const int rowIdx = idx >> HSH;
            const int row = rowIdx >> 4;
            const int ci  = rowIdx & 15;
            const int px  = (off < DIL) ? (4 - DIL + off) : (132 + off - DIL);
            const int gx  = x0 + ((off < DIL) ? (off - DIL) : (128 + off - DIL));
            const int gy  = gyOf(row);
            float v = 0.f;
            bool ok = ((unsigned)gy < HH && (unsigned)gx < WW);
            if (FCVT == 2 && xf) ok = ok && (ci0 + ci < 113);
            if (ok) {
                float raw = ibase[(size_t)ci*HWSZ + (size_t)gy*WW + gx];
                v = xf ? rndtf((FCVT == 2) ? raw*s_scale : raw) : raw;
            }
            ((float*)ibuf)[rowIdx*PWD + px] = v;
        }
    };

    // prologue
    if (PIPE) {
        fill_weights(0, s_wb[0]);
        fill_input(0, s_inb[0]);
        asm volatile("cp.async.commit_group;");
        fill_halo(0, s_inb[0]);
    }

#pragma unroll 1
    for (int i = 0; i < NCH; i++) {
        __syncthreads();
        if (PIPE) {
            if (i + 1 < NCH) {
                fill_weights(i+1, s_wb[(i+1) & 1]);
                fill_input(i+1, s_inb[(i+1) & 1]);
            }
            asm volatile("cp.async.commit_group;");
            if (i + 1 < NCH) fill_halo(i+1, s_inb[(i+1) & 1]);
            if (i + 1 < NCH) asm volatile("cp.async.wait_group 1;" ::: "memory");
            else             asm volatile("cp.async.wait_group 0;" ::: "memory");
        } else {
            fill_weights(i, s_wb[0]);
            fill_input(i, s_inb[0]);
            asm volatile("cp.async.commit_group;");
            fill_halo(i, s_inb[0]);
            asm volatile("cp.async.wait_group 0;" ::: "memory");
        }
        __syncthreads();

        const unsigned* s_in = s_inb[PIPE ? (i & 1) : 0];
        const unsigned* s_w  = s_wb [PIPE ? (i & 1) : 0];
#pragma unroll
        for (int ky=0; ky<3; ky++) {
#pragma unroll
            for (int kx=0; kx<3; kx++) {
                const int xoff = MBASE + kx*DIL + wn*WN;
                const int srow = (RY == 1) ? ky : (wy + ky*DIL);
#pragma unroll
                for (int ks=0; ks<KC/8; ks++) {
                    unsigned a[MTILES][4];
#pragma unroll
                    for (int mt=0; mt<MTILES; mt++) {
                        const uint4 av = *(const uint4*)(s_w +
                            ((((ky*3+kx)*2 + ks)*NBLK + wm*MTILES + mt)*32 + lane)*4);
                        a[mt][0] = av.x; a[mt][1] = av.y; a[mt][2] = av.z; a[mt][3] = av.w;
                    }
#pragma unroll
                    for (int nt=0; nt<NTILES; nt++) {
                        const unsigned* bb = s_in + (srow*KC + ks*8 + c)*PWD + xoff + nt*8 + g;
                        unsigned bv[2];
                        bv[0] = bb[0];
                        bv[1] = bb[4*PWD];
#pragma unroll
                        for (int mt=0; mt<MTILES; mt++)
                            mma8(acc[mt][nt], a[mt], bv);
                    }
                }
            }
        }
    }

    // epilogue -> NCHW
    const int y = y0 + wy;
#pragma unroll
    for (int mt=0; mt<MTILES; mt++) {
        const int co0 = wm*WM + mt*16 + g;
        const float b0v = bias ? bias[co0]     : 0.f;
        const float b1v = bias ? bias[co0 + 8] : 0.f;
        const size_t obase = ((size_t)(bz*CoutS + coutOff + co0))*HWSZ + (size_t)y*WW + x0 + wn*WN;
        float* o0 = out + obase;
        float* o1 = o0 + (size_t)8*HWSZ;
#pragma unroll
        for (int nt=0; nt<NTILES; nt++) {
            const int px = nt*8 + 2*c;
            float2 v0, v1;
            v0.x = acc[mt][nt][0] + b0v; v0.y = acc[mt][nt][1] + b0v;
            v1.x = acc[mt][nt][2] + b1v; v1.y = acc[mt][nt][3] + b1v;
            if (WMODE == 1) {
                v0.x = rndtf(v0.x); v0.y = rndtf(v0.y);
                v1.x = rndtf(v1.x); v1.y = rndtf(v1.y);
            }
            *(float2*)(o0 + px) = v0;
            *(float2*)(o1 + px) = v1;
            if (WMODE == 2) {
                float2 r0, r1;
                r0.x = rndtf(v0.x); r0.y = rndtf(v0.y);
                r1.x = rndtf(v1.x); r1.y = rndtf(v1.y);
                *(float2*)(out2 + obase + px) = r0;
                *(float2*)(out2 + obase + (size_t)8*HWSZ + px) = r1;
            }
        }
    }
}

// ---------------- tiny FFMA2 conv for the 16->2 head -----------------------
#define C_NT 128
#define C_TH 16
#define C_TW 64
#define C_CO 8

template<int DIL>
__global__ __launch_bounds__(C_NT, 3)
void conv3x3_kernel(const float* __restrict__ in, int Cin, int CinS, int cinOff,
                    const float* __restrict__ wgt, const float* __restrict__ bias,
                    float* __restrict__ out, int Cout, int CoutS, int coutOff)
{
    constexpr int TLW = C_TW + 2*DIL;
    constexpr int TLH = C_TH + 2*DIL;
    constexpr int NE  = (DIL==1) ? 5 : (DIL==2) ? 6 : 8;
    __shared__ __align__(16) float s_in[2][TLH*TLW];
    __shared__ __align__(16) ull   s_w2[2][C_CO*9];

    const int cb   = blockIdx.x * C_CO;
    const int tile = blockIdx.y;
    const int x0g  = (tile & 3) * C_TW;
    const int y0g  = (tile >> 2) * C_TH;
    const int b    = blockIdx.z;
    const int tid  = threadIdx.x;
    const int ty   = tid >> 3;
    const int xo   = (tid & 7) * 8;

    ull acc[C_CO][4];
#pragma unroll
    for (int co=0;co<C_CO;co++)
#pragma unroll
        for (int p=0;p<4;p++) acc[co][p] = 0ull;

    for (int ci0 = 0; ci0 < Cin; ci0 += 2) {
#pragma unroll
        for (int cc = 0; cc < 2; cc++) {
            const int ci = ci0 + cc;
            const float* ip = in + ((size_t)(b*CinS + cinOff + ci))*HWSZ;
            const bool cv = (ci < Cin);
            for (int idx = tid; idx < TLH*TLW; idx += C_NT) {
                int r = idx / TLW, cx = idx - r*TLW;
                int gy = y0g + r - DIL, gx = x0g + cx - DIL;
                float v = 0.f;
                if (cv && gy >= 0 && gy < HH && gx >= 0 && gx < WW) v = ip[gy*WW + gx];
                s_in[cc][idx] = v;
            }
        }
        for (int idx = tid; idx < 2*C_CO*9; idx += C_NT) {
            int cc = idx / (C_CO*9);
            int t  = idx - cc*(C_CO*9);
            int co = t / 9, k = t - co*9;
            int gci = ci0 + cc, gco = cb + co;
            float w = (gci < Cin && gco < Cout) ? wgt[((size_t)gco*Cin + gci)*9 + k] : 0.f;
            s_w2[cc][t] = pk2(w, w);
        }
        __syncthreads();
#pragma unroll
        for (int cc = 0; cc < 2; cc++) {
#pragma unroll
            for (int ky = 0; ky < 3; ky++) {
                const float* rowp = &s_in[cc][(ty + ky*DIL)*TLW + xo];
                ull E[NE];
#pragma unroll
                for (int i = 0; i < NE; i++) E[i] = *(const ull*)(rowp + 2*i);
                ull O[4];
                if (DIL == 1) {
#pragma unroll
                    for (int i = 0; i < 4; i++) O[i] = pk2(rowp[2*i+1], rowp[2*i+2]);
                }
#pragma unroll
                for (int kx = 0; kx < 3; kx++) {
                    ull vv[4];
                    if (DIL == 1) {
                        if (kx == 0)      { vv[0]=E[0]; vv[1]=E[1]; vv[2]=E[2]; vv[3]=E[3]; }
                        else if (kx == 1) { vv[0]=O[0]; vv[1]=O[1]; vv[2]=O[2]; vv[3]=O[3]; }
                        else              { vv[0]=E[1]; vv[1]=E[2]; vv[2]=E[3]; vv[3]=E[4]; }
                    } else {
                        const int base = kx*(DIL/2);
#pragma unroll
                        for (int p = 0; p < 4; p++) vv[p] = E[base + p];
                    }
#pragma unroll
                    for (int co = 0; co < C_CO; co++) {
                        ull w = s_w2[cc][co*9 + ky*3 + kx];
#pragma unroll
                        for (int p = 0; p < 4; p++) fma2(acc[co][p], w, vv[p]);
                    }
                }
            }
        }
        __syncthreads();
    }
#pragma unroll
    for (int co = 0; co < C_CO; co++) {
        int gco = cb + co;
        if (gco >= Cout) break;
        float bv = bias ? bias[gco] : 0.f;
        ull bv2 = pk2(bv, bv);
        float* op = out + ((size_t)(b*CoutS + coutOff + gco))*HWSZ + (y0g + ty)*WW + x0g + xo;
#pragma unroll
        for (int p = 0; p < 4; p++) {
            ull r = add2(acc[co][p], bv2);
            *(ull*)(op + 2*p) = r;
        }
    }
}

// ---------------- instance norm + leaky relu (in place, float4) ----------
__global__ void instnorm_lrelu_kernel(float* __restrict__ x, const float* __restrict__ gamma,
                                      const float* __restrict__ beta, int C, int rnd)
{
    const int bc = blockIdx.x;
    float4* p = (float4*)(x + (size_t)bc*HWSZ);
    const int N4 = HWSZ/4;
    const int tid = threadIdx.x;
    float s = 0.f, s2 = 0.f;
    for (int i = tid; i < N4; i += 256) {
        float4 v = p[i];
        s  += v.x + v.y + v.z + v.w;
        s2 += v.x*v.x + v.y*v.y + v.z*v.z + v.w*v.w;
    }
    __shared__ float rs[256], rq[256];
    rs[tid] = s; rq[tid] = s2; __syncthreads();
    for (int off = 128; off > 0; off >>= 1) {
        if (tid < off) { rs[tid] += rs[tid+off]; rq[tid] += rq[tid+off]; }
        __syncthreads();
    }
    const float mu  = rs[0]*(1.f/HWSZ);
    const float var = rq[0]*(1.f/HWSZ) - mu*mu;
    const float inv = rsqrtf(var + 1e-5f);
    const int c = bc % C;
    const float ga = gamma[c]*inv, be = beta[c];
    for (int i = tid; i < N4; i += 256) {
        float4 v = p[i];
        v.x = (v.x-mu)*ga + be; v.x = (v.x >= 0.f) ? v.x : 0.2f*v.x;
        v.y = (v.y-mu)*ga + be; v.y = (v.y >= 0.f) ? v.y : 0.2f*v.y;
        v.z = (v.z-mu)*ga + be; v.z = (v.z >= 0.f) ? v.z : 0.2f*v.z;
        v.w = (v.w-mu)*ga + be; v.w = (v.w >= 0.f) ? v.w : 0.2f*v.w;
        if (rnd) {
            v.x = rndtf(v.x); v.y = rndtf(v.y); v.z = rndtf(v.z); v.w = rndtf(v.w);
        }
        p[i] = v;
    }
}

// ---------------- fused separable gaussian blur (replicate pad) ----------
__global__ void blur_fused_kernel(const float* __restrict__ in, int CinS, int cinOff,
                                  float* __restrict__ out, int C)
{
    __shared__ float sraw[22*72];
    __shared__ float sh[22*64];
    const int bx = blockIdx.x, by = blockIdx.y, bc = blockIdx.z;
    const int b = bc / C, c = bc % C;
    const int tid = threadIdx.x;
    const float* ip = in + ((size_t)(b*CinS + cinOff + c))*HWSZ;

    for (int idx = tid; idx < 22*70; idx += 256) {
        int r = idx / 70, cc = idx - r*70;
        int gy = min(max(by*16 + r - 3, 0), HH-1);
        int gx = min(max(bx*64 + cc - 3, 0), WW-1);
        sraw[r*72 + cc] = ip[gy*WW + gx];
    }
    __syncthreads();
    for (int idx = tid; idx < 22*64; idx += 256) {
        int r = idx >> 6, x = idx & 63;
        const float* rp = &sraw[r*72 + x];
        float s = 0.f;
#pragma unroll
        for (int t = 0; t < 7; t++) s += GK[t]*rp[t];
        sh[r*64 + x] = s;
    }
    __syncthreads();
    for (int k = tid; k < 16*64; k += 256) {
        int r = k >> 6, x = k & 63;
        float s = 0.f;
#pragma unroll
        for (int t = 0; t < 7; t++) s += GK[t]*sh[(r+t)*64 + x];
        out[(size_t)bc*HWSZ + (size_t)(by*16 + r)*WW + bx*64 + x] = s;
    }
}

// ---------------- local correlation: 2 px/thread, window reuse, FFMA2 ------
#define CW 40
__global__ void corr_kernel(const float* __restrict__ f1s, const float* __restrict__ f2base,
                            float* __restrict__ out, float* __restrict__ lcsum)
{
    __shared__ float s1[22*CW];
    __shared__ float red[256];
    const int bx = blockIdx.x, by = blockIdx.y, b = blockIdx.z;
    const int tid = threadIdx.x;
    const int ty = tid >> 4, tx = tid & 15;
    const int gy = by*16 + ty, gx = bx*32 + tx*2;

    ull acc2[49];
#pragma unroll
    for (int k = 0; k < 49; k++) acc2[k] = 0ull;

    for (int c = 0; c < 64; c++) {
        const float* p1 = f1s    + ((size_t)(b*64  + c))*HWSZ;
        const float* p2 = f2base + ((size_t)(b*128 + 64 + c))*HWSZ;
        for (int idx = tid; idx < 22*CW; idx += 256) {
            int r = idx / CW, cc = idx - r*CW;
            int yy = by*16 + r - 3, xx = bx*32 + cc - 3;
            s1[idx] = (yy >= 0 && yy < HH && xx >= 0 && xx < WW) ? p1[yy*WW+xx] : 0.f;
        }
        __syncthreads();
        const float v2a = p2[gy*WW + gx];
        const float v2b = p2[gy*WW + gx + 1];
#pragma unroll
        for (int i = 0; i < 7; i++) {
            const float* row = &s1[(ty+i)*CW + tx*2];
            float r[8];
#pragma unroll
            for (int q = 0; q < 8; q++) r[q] = row[q];
#pragma unroll
            for (int j = 0; j < 7; j++) {
                float d0 = v2a - r[j];
                float d1 = v2b - r[j+1];
                ull d = pk2(d0, d1);
                fma2(acc2[i*7+j], d, d);
            }
        }
        __syncthreads();
    }
    float tsum = 0.f;
#pragma unroll
    for (int k = 0; k < 49; k++) {
        float lo, hi; up2(lo, hi, acc2[k]);
        float2 lc; lc.x = lo*(1.f/64.f); lc.y = hi*(1.f/64.f);
        *(float2*)&out[((size_t)(b*128 + 64 + k))*HWSZ + gy*WW + gx] = lc;
        tsum += lc.x + lc.y;
    }
    red[tid] = tsum; __syncthreads();
    for (int off = 128; off > 0; off >>= 1) {
        if (tid < off) red[tid] += red[tid+off];
        __syncthreads();
    }
    if (tid == 0) atomicAdd(&lcsum[b], red[0]);
}

__global__ void zero_lcsum_kernel(float* lcsum)
{
    if (threadIdx.x < BB) lcsum[threadIdx.x] = 0.f;
}

// ---------------- host side ----------------
template<int COUT, int CIN, int DIL, int WMODE, int FCVT, int RY>
static void launch_mma(const float* in, int CinS, int cinOff,
                       const float* wp, const float* bias,
                       float* out, int CoutS, int coutOff, float* out2,
                       const float* lcs)
{
    constexpr int NROWS = (RY == 1) ? 48 : (2 + 2*DIL)*16;
    constexpr int WCH = 9*16*COUT;
    const int smem = ((RY == 2 ? 2 : 1)*NROWS*PWD + (RY == 2 ? 2 : 1)*WCH)*4;
    cudaFuncSetAttribute(conv_mma<COUT,CIN,DIL,WMODE,FCVT,RY>,
                         cudaFuncAttributeMaxDynamicSharedMemorySize, smem);
    conv_mma<COUT,CIN,DIL,WMODE,FCVT,RY><<<dim3(2, HH/RY, BB), 256*RY, smem>>>(
        in, CinS, cinOff, wp, bias, out, CoutS, coutOff, out2, lcs);
}

extern "C" void kernel_launch(void* const* d_in, const int* in_sizes, int n_in,
                              void* d_out, int out_size)
{
    const float* feat1  = (const float*)d_in[0];
    const float* feat2  = (const float*)d_in[1];
    const float* pre_w  = (const float*)d_in[2];
    const float* pre_b  = (const float*)d_in[3];
    const float* fc1_w  = (const float*)d_in[4];
    const float* fc1_g  = (const float*)d_in[5];
    const float* fc1_be = (const float*)d_in[6];
    const float* fc2_w  = (const float*)d_in[7];
    const float* fc2_b  = (const float*)d_in[8];
    const float* e1_w   = (const float*)d_in[9];
    const float* e1_g   = (const float*)d_in[10];
    const float* e1_be  = (const float*)d_in[11];
    const float* e2_w   = (const float*)d_in[12];
    const float* e2_g   = (const float*)d_in[13];
    const float* e2_be  = (const float*)d_in[14];
    const float* e3_w   = (const float*)d_in[15];
    const float* e3_g   = (const float*)d_in[16];
    const float* e3_be  = (const float*)d_in[17];
    const float* head_w = (const float*)d_in[18];
    const float* head_b = (const float*)d_in[19];
    float* out = (float*)d_out;

    float *cat_, *cattf, *x128, *corr_, *f1s, *x64, *x32, *x16, *head_, *lcsum, *wpb;
    cudaGetSymbolAddress((void**)&cat_,  g_cat);
    cudaGetSymbolAddress((void**)&cattf, g_cattf);
    cudaGetSymbolAddress((void**)&x128,  g_x128);
    cudaGetSymbolAddress((void**)&corr_, g_corr);
    cudaGetSymbolAddress((void**)&f1s,   g_f1s);
    cudaGetSymbolAddress((void**)&x64,   g_x64);
    cudaGetSymbolAddress((void**)&x32,   g_x32);
    cudaGetSymbolAddress((void**)&x16,   g_x16);
    cudaGetSymbolAddress((void**)&head_, g_head);
    cudaGetSymbolAddress((void**)&lcsum, g_lcsum);
    cudaGetSymbolAddress((void**)&wpb,   g_wp);

    float* wp_pre = wpb;
    float* wp_fc1 = wpb + 36864;
    float* wp_fc2 = wpb + 184320;
    float* wp_e1  = wpb + 258048;
    float* wp_e2  = wpb + 331776;
    float* wp_e3  = wpb + 350208;

    // weight prep (fragment-swizzled, tf32, ci-padded)
    prep_all_kernel<<<(354816 + 255)/256, 256>>>(pre_w, fc1_w, fc2_w, e1_w, e2_w, e3_w, wpb);

    // preprocessor (cvt fill from raw feats) -> cat (raw) + cattf (rounded)
    launch_mma<64,64,1,2,1,2>(feat1, 64, 0, wp_pre, pre_b, cat_, 128, 0, cattf, nullptr);
    launch_mma<64,64,1,2,1,2>(feat2, 64, 0, wp_pre, pre_b, cat_, 128, 64, cattf, nullptr);

    // featcompressor layer1 + IN(+round)  (COUT=128: 256-thr single-buffer best)
    launch_mma<128,128,1,0,0,1>(cattf, 128, 0, wp_fc1, nullptr, x128, 128, 0, nullptr, nullptr);
    instnorm_lrelu_kernel<<<BB*128, 256>>>(x128, fc1_g, fc1_be, 128, 1);

    // featcompressor layer2 -> corr channels 0..63 (rounded)
    launch_mma<64,128,1,1,0,2>(x128, 128, 0, wp_fc2, fc2_b, corr_, 128, 0, nullptr, nullptr);

    // fused gaussian blur of f1 (raw cat)
    blur_fused_kernel<<<dim3(4, 16, BB*64), 256>>>(cat_, 128, 0, f1s, 64);

    // local correlation -> corr channels 64..112 (raw; normalized at e1 fill)
    zero_lcsum_kernel<<<1, 32>>>(lcsum);
    corr_kernel<<<dim3(WW/32, HH/16, BB), 256>>>(f1s, cat_, corr_, lcsum);

    // estimator stack (e1 fill scales+rounds lc channels via lcsum)
    launch_mma<64,128,1,0,2,2>(corr_, 128, 0, wp_e1, nullptr, x64, 64, 0, nullptr, lcsum);
    instnorm_lrelu_kernel<<<BB*64, 256>>>(x64, e1_g, e1_be, 64, 1);

    launch_mma<32,64,2,0,0,2>(x64, 64, 0, wp_e2, nullptr, x32, 32, 0, nullptr, nullptr);
    instnorm_lrelu_kernel<<<BB*32, 256>>>(x32, e2_g, e2_be, 32, 1);

    launch_mma<16,32,4,0,0,2>(x32, 32, 0, wp_e3, nullptr, x16, 16, 0, nullptr, nullptr);
    instnorm_lrelu_kernel<<<BB*16, 256>>>(x16, e3_g, e3_be, 16, 0);   // head needs raw

    // flow head (tiny, FFMA2 direct conv)
    {
        dim3 grid(1, (WW/C_TW)*(HH/C_TH), BB);
        conv3x3_kernel<1><<<grid, C_NT>>>(x16, 16, 16, 0, head_w, head_b, head_, 2, 2, 0);
    }

    // final fused blur -> output
    blur_fused_kernel<<<dim3(4, 16, BB*2), 256>>>(head_, 2, 0, out, 2);
}

// round 16
// speedup vs baseline: 1.2034x; 1.2034x over previous
#include <cuda_runtime.h>
#include <math.h>

// ---------------- problem constants ----------------
#define BB 4
#define HH 256
#define WW 256
#define HWSZ (HH*WW)

typedef unsigned long long ull;

// ---------------- scratch buffers ----------------
__device__ float g_cat   [(size_t)BB*128*HWSZ]; // raw f1|f2 (for blur/corr)
__device__ float g_cattf [(size_t)BB*128*HWSZ]; // tf32-rounded f1|f2 (for fc1)
__device__ float g_x128  [(size_t)BB*128*HWSZ];
__device__ float g_corr  [(size_t)BB*128*HWSZ]; // feat(rounded) | lc(raw) | zero
__device__ float g_f1s   [(size_t)BB*64*HWSZ];
__device__ float g_x64   [(size_t)BB*64*HWSZ];
__device__ float g_x32   [(size_t)BB*32*HWSZ];
__device__ float g_x16   [(size_t)BB*16*HWSZ];
__device__ float g_head  [(size_t)BB*2*HWSZ];
__device__ float g_lcsum[BB];
__device__ float g_wp[36864 + 147456 + 73728 + 73728 + 18432 + 4608];

__constant__ float GK[7] = {0.03663285f, 0.11128102f, 0.21674443f, 0.27068263f,
                            0.21674443f, 0.11128102f, 0.03663285f};

// ---------------- helpers ----------------
__device__ __forceinline__ unsigned f2tf(float f) {
    unsigned r; asm("cvt.rna.tf32.f32 %0, %1;" : "=r"(r) : "f"(f)); return r;
}
__device__ __forceinline__ float rndtf(float f) { return __uint_as_float(f2tf(f)); }
__device__ __forceinline__ void mma8(float* d, const unsigned* a, const unsigned* b) {
    asm volatile("mma.sync.aligned.m16n8k8.row.col.f32.tf32.tf32.f32 "
        "{%0,%1,%2,%3}, {%4,%5,%6,%7}, {%8,%9}, {%0,%1,%2,%3};\n"
        : "+f"(d[0]), "+f"(d[1]), "+f"(d[2]), "+f"(d[3])
        : "r"(a[0]), "r"(a[1]), "r"(a[2]), "r"(a[3]), "r"(b[0]), "r"(b[1]));
}
__device__ __forceinline__ ull pk2(float lo, float hi) {
    ull r; asm("mov.b64 %0, {%1, %2};" : "=l"(r) : "f"(lo), "f"(hi)); return r;
}
__device__ __forceinline__ void up2(float& lo, float& hi, ull v) {
    asm("mov.b64 {%0, %1}, %2;" : "=f"(lo), "=f"(hi) : "l"(v));
}
__device__ __forceinline__ void fma2(ull& d, ull a, ull b) {
    asm("fma.rn.f32x2 %0, %1, %2, %0;" : "+l"(d) : "l"(a), "l"(b));
}
__device__ __forceinline__ ull add2(ull a, ull b) {
    ull r; asm("add.rn.f32x2 %0, %1, %2;" : "=l"(r) : "l"(a), "l"(b)); return r;
}
__device__ __forceinline__ unsigned smem_u32(const void* p) {
    return (unsigned)__cvta_generic_to_shared(p);
}
__device__ __forceinline__ void cpasync16(unsigned dst, const void* src) {
    asm volatile("cp.async.cg.shared.global [%0], [%1], 16;" :: "r"(dst), "l"(src));
}
__device__ __forceinline__ void cpasync16_z(unsigned dst, const void* src) {
    asm volatile("cp.async.cg.shared.global [%0], [%1], 16, 0;" :: "r"(dst), "l"(src));
}

// ---------------- merged weight prep, fragment-swizzled layout -------------
__device__ __forceinline__ void prep_one(const float* src, float* dst, int r,
                                         int COUT, int CIN)
{
    int j     = r & 3;
    int lane  = (r >> 2) & 31;
    int t     = r >> 7;
    int nblk  = COUT >> 4;
    int coblk = t % nblk;  t /= nblk;
    int ks    = t & 1;     t >>= 1;
    int k9    = t % 9;
    int chunk = t / 9;
    int ci = chunk*16 + ks*8 + (lane & 3) + ((j >> 1) ? 4 : 0);
    int co = coblk*16 + (lane >> 2) + ((j & 1) ? 8 : 0);
    float v = (ci < CIN) ? src[((size_t)(co*CIN + ci))*9 + k9] : 0.f;
    dst[r] = rndtf(v);
}

__global__ void prep_all_kernel(const float* __restrict__ w_pre,
                                const float* __restrict__ w_fc1,
                                const float* __restrict__ w_fc2,
                                const float* __restrict__ w_e1,
                                const float* __restrict__ w_e2,
                                const float* __restrict__ w_e3,
                                float* __restrict__ wp)
{
    int idx = blockIdx.x*256 + threadIdx.x;
    if      (idx < 36864)  prep_one(w_pre, wp,          idx,          64, 64);
    else if (idx < 184320) prep_one(w_fc1, wp + 36864,  idx - 36864, 128, 128);
    else if (idx < 258048) prep_one(w_fc2, wp + 184320, idx - 184320, 64, 128);
    else if (idx < 331776) prep_one(w_e1,  wp + 258048, idx - 258048, 64, 113);
    else if (idx < 350208) prep_one(w_e2,  wp + 331776, idx - 331776, 32, 64);
    else if (idx < 354816) prep_one(w_e3,  wp + 350208, idx - 350208, 16, 32);
}

#define KC 16
#define PWD 136

// ======== variant A: 512 threads, 2 output rows per CTA (R12, best smalls) =
template<int COUT, int CIN, int DIL, int WMODE, int FCVT>
__global__ __launch_bounds__(512)
void conv_mma_r2(const float* __restrict__ in, int CinS, int cinOff,
                 const float* __restrict__ wp, const float* __restrict__ bias,
                 float* __restrict__ out, int CoutS, int coutOff,
                 float* __restrict__ out2, const float* __restrict__ lcs)
{
    constexpr int WM = (COUT >= 32) ? 32 : COUT;
    constexpr int NMW = COUT / WM;
    constexpr int NNW = 8 / NMW;
    constexpr int WN  = 128 / NNW;
    constexpr int MTILES = WM / 16;
    constexpr int NTILES = WN / 8;
    constexpr int NBLK = COUT / 16;
    constexpr int WCHUNK4 = 9*2*NBLK*32;
    constexpr int NR = 2 + 2*DIL;
    constexpr int HSH = (DIL==1) ? 1 : (DIL==2) ? 2 : 3;
    constexpr int NHALO = NR*KC*2*DIL;
    constexpr int MBASE = 4 - DIL;

    extern __shared__ __align__(16) unsigned smem_u[];
    unsigned* s_in = smem_u;                    // [NR*KC][PWD], main px at +4
    unsigned* s_w  = smem_u + NR*KC*PWD;        // [9][2][NBLK][32][4]

    const int tid = threadIdx.x;
    const int x0  = blockIdx.x * 128;
    const int y0  = blockIdx.y * 2;
    const int bz  = blockIdx.z;
    const int wid = tid >> 5, lane = tid & 31;
    const int g = lane >> 2, c = lane & 3;
    const int wy = wid >> 3;
    const int w8 = wid & 7;
    const int wm = w8 % NMW, wn = w8 / NMW;

    float s_scale = 1.f;
    if (FCVT == 2) {
        float mean = lcs[bz]*(1.f/(49.f*HWSZ));
        s_scale = 1.f/(mean + 1e-6f);
    }

    float acc[MTILES][NTILES][4];
#pragma unroll
    for (int mt=0; mt<MTILES; mt++)
#pragma unroll
        for (int nt=0; nt<NTILES; nt++)
#pragma unroll
            for (int r=0; r<4; r++) acc[mt][nt][r] = 0.f;

#pragma unroll 1
    for (int ci0 = 0; ci0 < CIN; ci0 += KC) {
        __syncthreads();
        {
            const float4* wsrc = (const float4*)wp + (size_t)(ci0 >> 4)*WCHUNK4;
            for (int idx = tid; idx < WCHUNK4; idx += 512)
                cpasync16(smem_u32((float*)s_w + idx*4), wsrc + idx);
        }
        const float* ibase = in + ((size_t)(bz*CinS + cinOff + ci0))*HWSZ;
        const bool async_chunk = (FCVT == 0) || (FCVT == 2 && ci0 < 64);
        if (async_chunk) {
#pragma unroll
            for (int it = 0; it < NR; it++) {
                const int idx    = tid + it*512;
                const int chunk  = idx & 31;
                const int rowIdx = idx >> 5;
                const int row = rowIdx >> 4;
                const int ci  = rowIdx & 15;
                const int gy  = y0 - DIL + row;
                unsigned dst = smem_u32((float*)s_in + rowIdx*PWD + 4 + chunk*4);
                const float* src = ibase + (size_t)ci*HWSZ
                                 + (size_t)min(max(gy,0),HH-1)*WW + x0 + chunk*4;
                if ((unsigned)gy < HH) cpasync16(dst, src);
                else                   cpasync16_z(dst, src);
            }
            asm volatile("cp.async.commit_group;");
            for (int idx = tid; idx < NHALO; idx += 512) {
                const int off    = idx & (2*DIL - 1);
                const int rowIdx = idx >> HSH;
                const int row = rowIdx >> 4;
                const int ci  = rowIdx & 15;
                const int px  = (off < DIL) ? (4 - DIL + off) : (132 + off - DIL);
                const int gx  = x0 + ((off < DIL) ? (off - DIL) : (128 + off - DIL));
                const int gy  = y0 - DIL + row;
                float v = 0.f;
                if ((unsigned)gy < HH && (unsigned)gx < WW)
                    v = ibase[(size_t)ci*HWSZ + (size_t)gy*WW + gx];
                ((float*)s_in)[rowIdx*PWD + px] = v;
            }
        } else {
            asm volatile("cp.async.commit_group;");
            const int pxm = tid & 127;
            const int r0  = tid >> 7;                 // 0..3
#pragma unroll
            for (int it = 0; it < NR*4; it++) {
                const int rowIdx = it*4 + r0;
                const int row = rowIdx >> 4;
                const int ci  = rowIdx & 15;
                const int gy  = y0 - DIL + row;
                const int gci = ci0 + ci;
                float v = 0.f;
                bool ok = ((unsigned)gy < HH);
                if (FCVT == 2) ok = ok && (gci < 113);
                if (ok) {
                    float raw = ibase[(size_t)ci*HWSZ + (size_t)gy*WW + x0 + pxm];
                    v = rndtf((FCVT == 2) ? raw*s_scale : raw);
                }
                s_in[rowIdx*PWD + 4 + pxm] = __float_as_uint(v);
            }
            for (int idx = tid; idx < NHALO; idx += 512) {
                const int off    = idx & (2*DIL - 1);
                const int rowIdx = idx >> HSH;
                const int row = rowIdx >> 4;
                const int ci  = rowIdx & 15;
                const int px  = (off < DIL) ? (4 - DIL + off) : (132 + off - DIL);
                const int gx  = x0 + ((off < DIL) ? (off - DIL) : (128 + off - DIL));
                const int gy  = y0 - DIL + row;
                const int gci = ci0 + ci;
                float v = 0.f;
                bool ok = ((unsigned)gy < HH && (unsigned)gx < WW);
                if (FCVT == 2) ok = ok && (gci < 113);
                if (ok) {
                    float raw = ibase[(size_t)ci*HWSZ + (size_t)gy*WW + gx];
                    v = rndtf((FCVT == 2) ? raw*s_scale : raw);
                }
                s_in[rowIdx*PWD + px] = __float_as_uint(v);
            }
        }
        asm volatile("cp.async.wait_group 0;" ::: "memory");
        __syncthreads();

#pragma unroll
        for (int ky=0; ky<3; ky++) {
#pragma unroll
            for (int kx=0; kx<3; kx++) {
                const int xoff = MBASE + kx*DIL + wn*WN;
                const int srow = wy + ky*DIL;
#pragma unroll
                for (int ks=0; ks<KC/8; ks++) {
                    unsigned a[MTILES][4];
#pragma unroll
                    for (int mt=0; mt<MTILES; mt++) {
                        const uint4 av = *(const uint4*)(s_w +
                            ((((ky*3+kx)*2 + ks)*NBLK + wm*MTILES + mt)*32 + lane)*4);
                        a[mt][0] = av.x; a[mt][1] = av.y; a[mt][2] = av.z; a[mt][3] = av.w;
                    }
#pragma unroll
                    for (int nt=0; nt<NTILES; nt++) {
                        const unsigned* bb = s_in + (srow*KC + ks*8 + c)*PWD + xoff + nt*8 + g;
                        unsigned bv[2];
                        bv[0] = bb[0];
                        bv[1] = bb[4*PWD];
#pragma unroll
                        for (int mt=0; mt<MTILES; mt++)
                            mma8(acc[mt][nt], a[mt], bv);
                    }
                }
            }
        }
    }

    const int y = y0 + wy;
#pragma unroll
    for (int mt=0; mt<MTILES; mt++) {
        const int co0 = wm*WM + mt*16 + g;
        const float b0v = bias ? bias[co0]     : 0.f;
        const float b1v = bias ? bias[co0 + 8] : 0.f;
        const size_t obase = ((size_t)(bz*CoutS + coutOff + co0))*HWSZ + (size_t)y*WW + x0 + wn*WN;
        float* o0 = out + obase;
        float* o1 = o0 + (size_t)8*HWSZ;
#pragma unroll
        for (int nt=0; nt<NTILES; nt++) {
            const int px = nt*8 + 2*c;
            float2 v0, v1;
            v0.x = acc[mt][nt][0] + b0v; v0.y = acc[mt][nt][1] + b0v;
            v1.x = acc[mt][nt][2] + b1v; v1.y = acc[mt][nt][3] + b1v;
            if (WMODE == 1) {
                v0.x = rndtf(v0.x); v0.y = rndtf(v0.y);
                v1.x = rndtf(v1.x); v1.y = rndtf(v1.y);
            }
            *(float2*)(o0 + px) = v0;
            *(float2*)(o1 + px) = v1;
            if (WMODE == 2) {
                float2 r0, r1;
                r0.x = rndtf(v0.x); r0.y = rndtf(v0.y);
                r1.x = rndtf(v1.x); r1.y = rndtf(v1.y);
                *(float2*)(out2 + obase + px) = r0;
                *(float2*)(out2 + obase + (size_t)8*HWSZ + px) = r1;
            }
        }
    }
}

// ======== variant B: 256 threads, 1 output row per CTA (R14, best fc1) =====
template<int COUT, int CIN, int DIL, int WMODE, int FCVT>
__global__ __launch_bounds__(256)
void conv_mma_r1(const float* __restrict__ in, int CinS, int cinOff,
                 const float* __restrict__ wp, const float* __restrict__ bias,
                 float* __restrict__ out, int CoutS, int coutOff,
                 float* __restrict__ out2, const float* __restrict__ lcs)
{
    constexpr int WM = (COUT >= 32) ? 32 : COUT;
    constexpr int NMW = COUT / WM;
    constexpr int NNW = 8 / NMW;
    constexpr int WN  = 128 / NNW;
    constexpr int MTILES = WM / 16;
    constexpr int NTILES = WN / 8;
    constexpr int NBLK = COUT / 16;
    constexpr int WCHUNK4 = 9*2*NBLK*32;
    constexpr int HSH = (DIL==1) ? 1 : (DIL==2) ? 2 : 3;
    constexpr int NHALO = 3*KC*2*DIL;
    constexpr int MBASE = 4 - DIL;

    extern __shared__ __align__(16) unsigned smem_u[];
    unsigned* s_in = smem_u;                    // [3*KC][PWD], main px at +4
    unsigned* s_w  = smem_u + 3*KC*PWD;         // [9][2][NBLK][32][4]

    const int tid = threadIdx.x;
    const int x0  = blockIdx.x * 128;
    const int y   = blockIdx.y;
    const int bz  = blockIdx.z;
    const int wid = tid >> 5, lane = tid & 31;
    const int g = lane >> 2, c = lane & 3;
    const int wm = wid % NMW, wn = wid / NMW;

    float s_scale = 1.f;
    if (FCVT == 2) {
        float mean = lcs[bz]*(1.f/(49.f*HWSZ));
        s_scale = 1.f/(mean + 1e-6f);
    }

    float acc[MTILES][NTILES][4];
#pragma unroll
    for (int mt=0; mt<MTILES; mt++)
#pragma unroll
        for (int nt=0; nt<NTILES; nt++)
#pragma unroll
            for (int r=0; r<4; r++) acc[mt][nt][r] = 0.f;

#pragma unroll 1
    for (int ci0 = 0; ci0 < CIN; ci0 += KC) {
        __syncthreads();
        {
            const float4* wsrc = (const float4*)wp + (size_t)(ci0 >> 4)*WCHUNK4;
            for (int idx = tid; idx < WCHUNK4; idx += 256)
                cpasync16(smem_u32((float*)s_w + idx*4), wsrc + idx);
        }
        const float* ibase = in + ((size_t)(bz*CinS + cinOff + ci0))*HWSZ;
        const bool async_chunk = (FCVT == 0) || (FCVT == 2 && ci0 < 64);
        if (async_chunk) {
#pragma unroll
            for (int it = 0; it < 6; it++) {
                const int idx    = tid + it*256;
                const int chunk  = idx & 31;
                const int rowIdx = idx >> 5;          // 0..47
                const int row = rowIdx >> 4;
                const int ci  = rowIdx & 15;
                const int gy  = y + (row-1)*DIL;
                unsigned dst = smem_u32((float*)s_in + rowIdx*PWD + 4 + chunk*4);
                const float* src = ibase + (size_t)ci*HWSZ
                                 + (size_t)min(max(gy,0),HH-1)*WW + x0 + chunk*4;
                if ((unsigned)gy < HH) cpasync16(dst, src);
                else                   cpasync16_z(dst, src);
            }
            asm volatile("cp.async.commit_group;");
            for (int idx = tid; idx < NHALO; idx += 256) {
                const int off    = idx & (2*DIL - 1);
                const int rowIdx = idx >> HSH;
                const int row = rowIdx >> 4;
                const int ci  = rowIdx & 15;
                const int px  = (off < DIL) ? (4 - DIL + off) : (132 + off - DIL);
                const int gx  = x0 + ((off < DIL) ? (off - DIL) : (128 + off - DIL));
                const int gy  = y + (row-1)*DIL;
                float v = 0.f;
                if ((unsigned)gy < HH && (unsigned)gx < WW)
                    v = ibase[(size_t)ci*HWSZ + (size_t)gy*WW + gx];
                ((float*)s_in)[rowIdx*PWD + px] = v;
            }
        } else {
            asm volatile("cp.async.commit_group;");
            const int pxm = tid & 127;
            const int r0  = tid >> 7;                 // 0/1
#pragma unroll
            for (int it = 0; it < 24; it++) {
                const int rowIdx = it*2 + r0;
                const int row = rowIdx >> 4;
                const int ci  = rowIdx & 15;
                const int gy  = y + (row-1)*DIL;
                const int gci = ci0 + ci;
                float v = 0.f;
                bool ok = ((unsigned)gy < HH);
                if (FCVT == 2) ok = ok && (gci < 113);
                if (ok) {
                    float raw = ibase[(size_t)ci*HWSZ + (size_t)gy*WW + x0 + pxm];
                    v = rndtf((FCVT == 2) ? raw*s_scale : raw);
                }
                s_in[rowIdx*PWD + 4 + pxm] = __float_as_uint(v);
            }
            for (int idx = tid; idx < NHALO; idx += 256) {
                const int off    = idx & (2*DIL - 1);
                const int rowIdx = idx >> HSH;
                const int row = rowIdx >> 4;
                const int ci  = rowIdx & 15;
                const int px  = (off < DIL) ? (4 - DIL + off) : (132 + off - DIL);
                const int gx  = x0 + ((off < DIL) ? (off - DIL) : (128 + off - DIL));
                const int gy  = y + (row-1)*DIL;
                const int gci = ci0 + ci;
                float v = 0.f;
                bool ok = ((unsigned)gy < HH && (unsigned)gx < WW);
                if (FCVT == 2) ok = ok && (gci < 113);
                if (ok) {
                    float raw = ibase[(size_t)ci*HWSZ + (size_t)gy*WW + gx];
                    v = rndtf((FCVT == 2) ? raw*s_scale : raw);
                }
                s_in[rowIdx*PWD + px] = __float_as_uint(v);
            }
        }
        asm volatile("cp.async.wait_group 0;" ::: "memory");
        __syncthreads();

#pragma unroll
        for (int ky=0; ky<3; ky++) {
#pragma unroll
            for (int kx=0; kx<3; kx++) {
                const int xoff = MBASE + kx*DIL + wn*WN;
#pragma unroll
                for (int ks=0; ks<KC/8; ks++) {
                    unsigned a[MTILES][4];
#pragma unroll
                    for (int mt=0; mt<MTILES; mt++) {
                        const uint4 av = *(const uint4*)(s_w +
                            ((((ky*3+kx)*2 + ks)*NBLK + wm*MTILES + mt)*32 + lane)*4);
                        a[mt][0] = av.x; a[mt][1] = av.y; a[mt][2] = av.z; a[mt][3] = av.w;
                    }
#pragma unroll
                    for (int nt=0; nt<NTILES; nt++) {
                        const unsigned* bb = s_in + (ky*KC + ks*8 + c)*PWD + xoff + nt*8 + g;
                        unsigned bv[2];
                        bv[0] = bb[0];
                        bv[1] = bb[4*PWD];
#pragma unroll
                        for (int mt=0; mt<MTILES; mt++)
                            mma8(acc[mt][nt], a[mt], bv);
                    }
                }
            }
        }
    }

#pragma unroll
    for (int mt=0; mt<MTILES; mt++) {
        const int co0 = wm*WM + mt*16 + g;
        const float b0v = bias ? bias[co0]     : 0.f;
        const float b1v = bias ? bias[co0 + 8] : 0.f;
        const size_t obase = ((size_t)(bz*CoutS + coutOff + co0))*HWSZ + (size_t)y*WW + x0 + wn*WN;
        float* o0 = out + obase;
        float* o1 = o0 + (size_t)8*HWSZ;
#pragma unroll
        for (int nt=0; nt<NTILES; nt++) {
            const int px = nt*8 + 2*c;
            float2 v0, v1;
            v0.x = acc[mt][nt][0] + b0v; v0.y = acc[mt][nt][1] + b0v;
            v1.x = acc[mt][nt][2] + b1v; v1.y = acc[mt][nt][3] + b1v;
            if (WMODE == 1) {
                v0.x = rndtf(v0.x); v0.y = rndtf(v0.y);
                v1.x = rndtf(v1.x); v1.y = rndtf(v1.y);
            }
            *(float2*)(o0 + px) = v0;
            *(float2*)(o1 + px) = v1;
            if (WMODE == 2) {
                float2 r0, r1;
                r0.x = rndtf(v0.x); r0.y = rndtf(v0.y);
                r1.x = rndtf(v1.x); r1.y = rndtf(v1.y);
                *(float2*)(out2 + obase + px) = r0;
                *(float2*)(out2 + obase + (size_t)8*HWSZ + px) = r1;
            }
        }
    }
}

// ---------------- tiny FFMA2 conv for the 16->2 head -----------------------
#define C_NT 128
#define C_TH 16
#define C_TW 64
#define C_CO 8

template<int DIL>
__global__ __launch_bounds__(C_NT, 3)
void conv3x3_kernel(const float* __restrict__ in, int Cin, int CinS, int cinOff,
                    const float* __restrict__ wgt, const float* __restrict__ bias,
                    float* __restrict__ out, int Cout, int CoutS, int coutOff)
{
    constexpr int TLW = C_TW + 2*DIL;
    constexpr int TLH = C_TH + 2*DIL;
    constexpr int NE  = (DIL==1) ? 5 : (DIL==2) ? 6 : 8;
    __shared__ __align__(16) float s_in[2][TLH*TLW];
    __shared__ __align__(16) ull   s_w2[2][C_CO*9];

    const int cb   = blockIdx.x * C_CO;
    const int tile = blockIdx.y;
    const int x0g  = (tile & 3) * C_TW;
    const int y0g  = (tile >> 2) * C_TH;
    const int b    = blockIdx.z;
    const int tid  = threadIdx.x;
    const int ty   = tid >> 3;
    const int xo   = (tid & 7) * 8;

    ull acc[C_CO][4];
#pragma unroll
    for (int co=0;co<C_CO;co++)
#pragma unroll
        for (int p=0;p<4;p++) acc[co][p] = 0ull;

    for (int ci0 = 0; ci0 < Cin; ci0 += 2) {
#pragma unroll
        for (int cc = 0; cc < 2; cc++) {
            const int ci = ci0 + cc;
            const float* ip = in + ((size_t)(b*CinS + cinOff + ci))*HWSZ;
            const bool cv = (ci < Cin);
            for (int idx = tid; idx < TLH*TLW; idx += C_NT) {
                int r = idx / TLW, cx = idx - r*TLW;
                int gy = y0g + r - DIL, gx = x0g + cx - DIL;
                float v = 0.f;
                if (cv && gy >= 0 && gy < HH && gx >= 0 && gx < WW) v = ip[gy*WW + gx];
                s_in[cc][idx] = v;
            }
        }
        for (int idx = tid; idx < 2*C_CO*9; idx += C_NT) {
            int cc = idx / (C_CO*9);
            int t  = idx - cc*(C_CO*9);
            int co = t / 9, k = t - co*9;
            int gci = ci0 + cc, gco = cb + co;
            float w = (gci < Cin && gco < Cout) ? wgt[((size_t)gco*Cin + gci)*9 + k] : 0.f;
            s_w2[cc][t] = pk2(w, w);
        }
        __syncthreads();
#pragma unroll
        for (int cc = 0; cc < 2; cc++) {
#pragma unroll
            for (int ky = 0; ky < 3; ky++) {
                const float* rowp = &s_in[cc][(ty + ky*DIL)*TLW + xo];
                ull E[NE];
#pragma unroll
                for (int i = 0; i < NE; i++) E[i] = *(const ull*)(rowp + 2*i);
                ull O[4];
                if (DIL == 1) {
#pragma unroll
                    for (int i = 0; i < 4; i++) O[i] = pk2(rowp[2*i+1], rowp[2*i+2]);
                }
#pragma unroll
                for (int kx = 0; kx < 3; kx++) {
                    ull vv[4];
                    if (DIL == 1) {
                        if (kx == 0)      { vv[0]=E[0]; vv[1]=E[1]; vv[2]=E[2]; vv[3]=E[3]; }
                        else if (kx == 1) { vv[0]=O[0]; vv[1]=O[1]; vv[2]=O[2]; vv[3]=O[3]; }
                        else              { vv[0]=E[1]; vv[1]=E[2]; vv[2]=E[3]; vv[3]=E[4]; }
                    } else {
                        const int base = kx*(DIL/2);
#pragma unroll
                        for (int p = 0; p < 4; p++) vv[p] = E[base + p];
                    }
#pragma unroll
                    for (int co = 0; co < C_CO; co++) {
                        ull w = s_w2[cc][co*9 + ky*3 + kx];
#pragma unroll
                        for (int p = 0; p < 4; p++) fma2(acc[co][p], w, vv[p]);
                    }
                }
            }
        }
        __syncthreads();
    }
#pragma unroll
    for (int co = 0; co < C_CO; co++) {
        int gco = cb + co;
        if (gco >= Cout) break;
        float bv = bias ? bias[gco] : 0.f;
        ull bv2 = pk2(bv, bv);
        float* op = out + ((size_t)(b*CoutS + coutOff + gco))*HWSZ + (y0g + ty)*WW + x0g + xo;
#pragma unroll
        for (int p = 0; p < 4; p++) {
            ull r = add2(acc[co][p], bv2);
            *(ull*)(op + 2*p) = r;
        }
    }
}

// ---------------- instance norm + leaky relu (in place, float4) ----------
__global__ void instnorm_lrelu_kernel(float* __restrict__ x, const float* __restrict__ gamma,
                                      const float* __restrict__ beta, int C, int rnd)
{
    const int bc = blockIdx.x;
    float4* p = (float4*)(x + (size_t)bc*HWSZ);
    const int N4 = HWSZ/4;
    const int tid = threadIdx.x;
    float s = 0.f, s2 = 0.f;
    for (int i = tid; i < N4; i += 256) {
        float4 v = p[i];
        s  += v.x + v.y + v.z + v.w;
        s2 += v.x*v.x + v.y*v.y + v.z*v.z + v.w*v.w;
    }
    __shared__ float rs[256], rq[256];
    rs[tid] = s; rq[tid] = s2; __syncthreads();
    for (int off = 128; off > 0; off >>= 1) {
        if (tid < off) { rs[tid] += rs[tid+off]; rq[tid] += rq[tid+off]; }
        __syncthreads();
    }
    const float mu  = rs[0]*(1.f/HWSZ);
    const float var = rq[0]*(1.f/HWSZ) - mu*mu;
    const float inv = rsqrtf(var + 1e-5f);
    const int c = bc % C;
    const float ga = gamma[c]*inv, be = beta[c];
    for (int i = tid; i < N4; i += 256) {
        float4 v = p[i];
        v.x = (v.x-mu)*ga + be; v.x = (v.x >= 0.f) ? v.x : 0.2f*v.x;
        v.y = (v.y-mu)*ga + be; v.y = (v.y >= 0.f) ? v.y : 0.2f*v.y;
        v.z = (v.z-mu)*ga + be; v.z = (v.z >= 0.f) ? v.z : 0.2f*v.z;
        v.w = (v.w-mu)*ga + be; v.w = (v.w >= 0.f) ? v.w : 0.2f*v.w;
        if (rnd) {
            v.x = rndtf(v.x); v.y = rndtf(v.y); v.z = rndtf(v.z); v.w = rndtf(v.w);
        }
        p[i] = v;
    }
}

// ---------------- fused separable gaussian blur (replicate pad) ----------
__global__ void blur_fused_kernel(const float* __restrict__ in, int CinS, int cinOff,
                                  float* __restrict__ out, int C)
{
    __shared__ float sraw[22*72];
    __shared__ float sh[22*64];
    const int bx = blockIdx.x, by = blockIdx.y, bc = blockIdx.z;
    const int b = bc / C, c = bc % C;
    const int tid = threadIdx.x;
    const float* ip = in + ((size_t)(b*CinS + cinOff + c))*HWSZ;

    for (int idx = tid; idx < 22*70; idx += 256) {
        int r = idx / 70, cc = idx - r*70;
        int gy = min(max(by*16 + r - 3, 0), HH-1);
        int gx = min(max(bx*64 + cc - 3, 0), WW-1);
        sraw[r*72 + cc] = ip[gy*WW + gx];
    }
    __syncthreads();
    for (int idx = tid; idx < 22*64; idx += 256) {
        int r = idx >> 6, x = idx & 63;
        const float* rp = &sraw[r*72 + x];
        float s = 0.f;
#pragma unroll
        for (int t = 0; t < 7; t++) s += GK[t]*rp[t];
        sh[r*64 + x] = s;
    }
    __syncthreads();
    for (int k = tid; k < 16*64; k += 256) {
        int r = k >> 6, x = k & 63;
        float s = 0.f;
#pragma unroll
        for (int t = 0; t < 7; t++) s += GK[t]*sh[(r+t)*64 + x];
        out[(size_t)bc*HWSZ + (size_t)(by*16 + r)*WW + bx*64 + x] = s;
    }
}

// ---------------- local correlation: 2 px/thread, window reuse, FFMA2 ------
#define CW 40
__global__ void corr_kernel(const float* __restrict__ f1s, const float* __restrict__ f2base,
                            float* __restrict__ out, float* __restrict__ lcsum)
{
    __shared__ float s1[22*CW];
    __shared__ float red[256];
    const int bx = blockIdx.x, by = blockIdx.y, b = blockIdx.z;
    const int tid = threadIdx.x;
    const int ty = tid >> 4, tx = tid & 15;
    const int gy = by*16 + ty, gx = bx*32 + tx*2;

    ull acc2[49];
#pragma unroll
    for (int k = 0; k < 49; k++) acc2[k] = 0ull;

    for (int c = 0; c < 64; c++) {
        const float* p1 = f1s    + ((size_t)(b*64  + c))*HWSZ;
        const float* p2 = f2base + ((size_t)(b*128 + 64 + c))*HWSZ;
        for (int idx = tid; idx < 22*CW; idx += 256) {
            int r = idx / CW, cc = idx - r*CW;
            int yy = by*16 + r - 3, xx = bx*32 + cc - 3;
            s1[idx] = (yy >= 0 && yy < HH && xx >= 0 && xx < WW) ? p1[yy*WW+xx] : 0.f;
        }
        __syncthreads();
        const float v2a = p2[gy*WW + gx];
        const float v2b = p2[gy*WW + gx + 1];
#pragma unroll
        for (int i = 0; i < 7; i++) {
            const float* row = &s1[(ty+i)*CW + tx*2];
            float r[8];
#pragma unroll
            for (int q = 0; q < 8; q++) r[q] = row[q];
#pragma unroll
            for (int j = 0; j < 7; j++) {
                float d0 = v2a - r[j];
                float d1 = v2b - r[j+1];
                ull d = pk2(d0, d1);
                fma2(acc2[i*7+j], d, d);
            }
        }
        __syncthreads();
    }
    float tsum = 0.f;
#pragma unroll
    for (int k = 0; k < 49; k++) {
        float lo, hi; up2(lo, hi, acc2[k]);
        float2 lc; lc.x = lo*(1.f/64.f); lc.y = hi*(1.f/64.f);
        *(float2*)&out[((size_t)(b*128 + 64 + k))*HWSZ + gy*WW + gx] = lc;
        tsum += lc.x + lc.y;
    }
    red[tid] = tsum; __syncthreads();
    for (int off = 128; off > 0; off >>= 1) {
        if (tid < off) red[tid] += red[tid+off];
        __syncthreads();
    }
    if (tid == 0) atomicAdd(&lcsum[b], red[0]);
}

__global__ void zero_lcsum_kernel(float* lcsum)
{
    if (threadIdx.x < BB) lcsum[threadIdx.x] = 0.f;
}

// ---------------- host side ----------------
template<int COUT, int CIN, int DIL, int WMODE, int FCVT>
static void launch_mma_r2(const float* in, int CinS, int cinOff,
                          const float* wp, const float* bias,
                          float* out, int CoutS, int coutOff, float* out2,
                          const float* lcs)
{
    constexpr int NR = 2 + 2*DIL;
    const int smem = (NR*KC*PWD + 9*2*(COUT/16)*128)*4;
    cudaFuncSetAttribute(conv_mma_r2<COUT,CIN,DIL,WMODE,FCVT>,
                         cudaFuncAttributeMaxDynamicSharedMemorySize, smem);
    conv_mma_r2<COUT,CIN,DIL,WMODE,FCVT><<<dim3(2, HH/2, BB), 512, smem>>>(
        in, CinS, cinOff, wp, bias, out, CoutS, coutOff, out2, lcs);
}

template<int COUT, int CIN, int DIL, int WMODE, int FCVT>
static void launch_mma_r1(const float* in, int CinS, int cinOff,
                          const float* wp, const float* bias,
                          float* out, int CoutS, int coutOff, float* out2,
                          const float* lcs)
{
    const int smem = (3*KC*PWD + 9*2*(COUT/16)*128)*4;
    cudaFuncSetAttribute(conv_mma_r1<COUT,CIN,DIL,WMODE,FCVT>,
                         cudaFuncAttributeMaxDynamicSharedMemorySize, smem);
    conv_mma_r1<COUT,CIN,DIL,WMODE,FCVT><<<dim3(2, HH, BB), 256, smem>>>(
        in, CinS, cinOff, wp, bias, out, CoutS, coutOff, out2, lcs);
}

extern "C" void kernel_launch(void* const* d_in, const int* in_sizes, int n_in,
                              void* d_out, int out_size)
{
    const float* feat1  = (const float*)d_in[0];
    const float* feat2  = (const float*)d_in[1];
    const float* pre_w  = (const float*)d_in[2];
    const float* pre_b  = (const float*)d_in[3];
    const float* fc1_w  = (const float*)d_in[4];
    const float* fc1_g  = (const float*)d_in[5];
    const float* fc1_be = (const float*)d_in[6];
    const float* fc2_w  = (const float*)d_in[7];
    const float* fc2_b  = (const float*)d_in[8];
    const float* e1_w   = (const float*)d_in[9];
    const float* e1_g   = (const float*)d_in[10];
    const float* e1_be  = (const float*)d_in[11];
    const float* e2_w   = (const float*)d_in[12];
    const float* e2_g   = (const float*)d_in[13];
    const float* e2_be  = (const float*)d_in[14];
    const float* e3_w   = (const float*)d_in[15];
    const float* e3_g   = (const float*)d_in[16];
    const float* e3_be  = (const float*)d_in[17];
    const float* head_w = (const float*)d_in[18];
    const float* head_b = (const float*)d_in[19];
    float* out = (float*)d_out;

    float *cat_, *cattf, *x128, *corr_, *f1s, *x64, *x32, *x16, *head_, *lcsum, *wpb;
    cudaGetSymbolAddress((void**)&cat_,  g_cat);
    cudaGetSymbolAddress((void**)&cattf, g_cattf);
    cudaGetSymbolAddress((void**)&x128,  g_x128);
    cudaGetSymbolAddress((void**)&corr_, g_corr);
    cudaGetSymbolAddress((void**)&f1s,   g_f1s);
    cudaGetSymbolAddress((void**)&x64,   g_x64);
    cudaGetSymbolAddress((void**)&x32,   g_x32);
    cudaGetSymbolAddress((void**)&x16,   g_x16);
    cudaGetSymbolAddress((void**)&head_, g_head);
    cudaGetSymbolAddress((void**)&lcsum, g_lcsum);
    cudaGetSymbolAddress((void**)&wpb,   g_wp);

    float* wp_pre = wpb;
    float* wp_fc1 = wpb + 36864;
    float* wp_fc2 = wpb + 184320;
    float* wp_e1  = wpb + 258048;
    float* wp_e2  = wpb + 331776;
    float* wp_e3  = wpb + 350208;

    // weight prep (fragment-swizzled, tf32, ci-padded)
    prep_all_kernel<<<(354816 + 255)/256, 256>>>(pre_w, fc1_w, fc2_w, e1_w, e2_w, e3_w, wpb);

    // preprocessor (cvt fill from raw feats) -> cat (raw) + cattf (rounded)
    launch_mma_r2<64,64,1,2,1>(feat1, 64, 0, wp_pre, pre_b, cat_, 128, 0, cattf, nullptr);
    launch_mma_r2<64,64,1,2,1>(feat2, 64, 0, wp_pre, pre_b, cat_, 128, 64, cattf, nullptr);

    // featcompressor layer1 + IN(+round)  (COUT=128: 256-thr variant best)
    launch_mma_r1<128,128,1,0,0>(cattf, 128, 0, wp_fc1, nullptr, x128, 128, 0, nullptr, nullptr);
    instnorm_lrelu_kernel<<<BB*128, 256>>>(x128, fc1_g, fc1_be, 128, 1);

    // featcompressor layer2 -> corr channels 0..63 (rounded)
    launch_mma_r2<64,128,1,1,0>(x128, 128, 0, wp_fc2, fc2_b, corr_, 128, 0, nullptr, nullptr);

    // fused gaussian blur of f1 (raw cat)
    blur_fused_kernel<<<dim3(4, 16, BB*64), 256>>>(cat_, 128, 0, f1s, 64);

    // local correlation -> corr channels 64..112 (raw; normalized at e1 fill)
    zero_lcsum_kernel<<<1, 32>>>(lcsum);
    corr_kernel<<<dim3(WW/32, HH/16, BB), 256>>>(f1s, cat_, corr_, lcsum);

    // estimator stack (e1 fill scales+rounds lc channels via lcsum)
    launch_mma_r2<64,128,1,0,2>(corr_, 128, 0, wp_e1, nullptr, x64, 64, 0, nullptr, lcsum);
    instnorm_lrelu_kernel<<<BB*64, 256>>>(x64, e1_g, e1_be, 64, 1);

    launch_mma_r2<32,64,2,0,0>(x64, 64, 0, wp_e2, nullptr, x32, 32, 0, nullptr, nullptr);
    instnorm_lrelu_kernel<<<BB*32, 256>>>(x32, e2_g, e2_be, 32, 1);

    launch_mma_r2<16,32,4,0,0>(x32, 32, 0, wp_e3, nullptr, x16, 16, 0, nullptr, nullptr);
    instnorm_lrelu_kernel<<<BB*16, 256>>>(x16, e3_g, e3_be, 16, 0);   // head needs raw

    // flow head (tiny, FFMA2 direct conv)
    {
        dim3 grid(1, (WW/C_TW)*(HH/C_TH), BB);
        conv3x3_kernel<1><<<grid, C_NT>>>(x16, 16, 16, 0, head_w, head_b, head_, 2, 2, 0);
    }

    // final fused blur -> output
    blur_fused_kernel<<<dim3(4, 16, BB*2), 256>>>(head_, 2, 0, out, 2);
}